// round 8
// baseline (speedup 1.0000x reference)
#include <cuda_runtime.h>
#include <cstdint>

#define BATCH 512
#define CHANNELS 256
#define KXS 6
#define KZ 22
#define HO 17
#define OUT_PER_B 289

#define CH_CHUNK 16                 // channels per chunk = 8 pairs
#define PAIRS_C 8
#define ITERS (CHANNELS/CH_CHUNK)   // 16
#define THREADS 272                 // 17 rows x (8 pairs x 2 ky-halves)
#define LANES 16

#define ZPAIR_FLOATS (KZ*KZ*2)      // 968
#define ZROW_PAIRF 44
#define XPAIR_FLOATS (KXS*KXS*2)    // 72
#define ZBUF_FLOATS (PAIRS_C*ZPAIR_FLOATS)   // 7744
#define XBUF_FLOATS (PAIRS_C*XPAIR_FLOATS)   // 576
#define BUF_FLOATS (ZBUF_FLOATS + XBUF_FLOATS)   // 8320
#define SMEM_BYTES (2*BUF_FLOATS*4)              // 66560

#define Z_UNITS (PAIRS_C*121)       // 968
#define X_UNITS (PAIRS_C*9)         // 72
#define PFK 4

typedef unsigned long long ull;

__device__ __forceinline__ void fma2(ull& d, ull a, ull b) {
    asm("fma.rn.f32x2 %0, %1, %2, %0;" : "+l"(d) : "l"(a), "l"(b));
}
__device__ __forceinline__ void unpack2(ull v, float& lo, float& hi) {
    asm("mov.b64 {%0, %1}, %2;" : "=f"(lo), "=f"(hi) : "l"(v));
}

__global__ __launch_bounds__(THREADS, 3)
void corr_main_kernel(const float* __restrict__ x, const float* __restrict__ z,
                      float* __restrict__ out)
{
    extern __shared__ float smem[];   // ping-pong buffers

    const int tid  = threadIdx.x;
    const int i    = tid % HO;        // output row
    const int lane = tid / HO;        // 0..15
    const int p    = lane >> 1;       // pair 0..7
    const int h    = lane & 1;        // ky half
    const int b    = blockIdx.x;

    // chunk-invariant staging map
    int zsrc_off[PFK], zdst_off[PFK];
    #pragma unroll
    for (int k = 0; k < PFK; k++) {
        int u = tid + k * THREADS;
        if (u < Z_UNITS) {
            int pu = u / 121;
            int w4 = u - pu * 121;
            zsrc_off[k] = 2 * pu * 121 + w4;
            zdst_off[k] = pu * ZPAIR_FLOATS + 8 * w4;
        } else { zsrc_off[k] = -1; zdst_off[k] = 0; }
    }
    int xsrc_off = -1, xdst_off = 0;
    if (tid < X_UNITS) {
        int pu = tid / 9, w4 = tid - pu * 9;
        xsrc_off = 2 * pu * 9 + w4;
        xdst_off = pu * XPAIR_FLOATS + 8 * w4;
    }

    const float4* zg = reinterpret_cast<const float4*>(
        z + (size_t)b * CHANNELS * (KZ * KZ));
    const float4* xg = reinterpret_cast<const float4*>(
        x + (size_t)b * CHANNELS * (KXS * KXS));
    const int ZCHUNK_STRIDE = CH_CHUNK * (KZ * KZ) / 4;   // 1936
    const int XCHUNK_STRIDE = CH_CHUNK * (KXS * KXS) / 4; // 144

    // ---- stage chunk 0 into buf0 (LDG -> interleave -> STS, transient regs) ----
    {
        float* zb0 = smem;
        float* xb0 = smem + ZBUF_FLOATS;
        #pragma unroll
        for (int k = 0; k < PFK; k++)
            if (zsrc_off[k] >= 0) {
                float4 a = zg[zsrc_off[k]];
                float4 c = zg[zsrc_off[k] + 121];
                float4* d4 = reinterpret_cast<float4*>(zb0 + zdst_off[k]);
                d4[0] = make_float4(a.x, c.x, a.y, c.y);
                d4[1] = make_float4(a.z, c.z, a.w, c.w);
            }
        if (xsrc_off >= 0) {
            float4 a = xg[xsrc_off];
            float4 c = xg[xsrc_off + 9];
            float4* d4 = reinterpret_cast<float4*>(xb0 + xdst_off);
            d4[0] = make_float4(a.x, c.x, a.y, c.y);
            d4[1] = make_float4(a.z, c.z, a.w, c.w);
        }
    }
    __syncthreads();

    ull acc[HO];
    #pragma unroll
    for (int j = 0; j < HO; j++) acc[j] = 0ull;

    #pragma unroll 1
    for (int it = 0; it < ITERS; ++it) {
        // ---- stage chunk it+1 into the other buffer (stall covered by other warps/CTAs) ----
        if (it + 1 < ITERS) {
            const float4* zpn = zg + (size_t)(it + 1) * ZCHUNK_STRIDE;
            const float4* xpn = xg + (size_t)(it + 1) * XCHUNK_STRIDE;
            float* zbn = smem + ((it + 1) & 1) * BUF_FLOATS;
            float* xbn = zbn + ZBUF_FLOATS;
            #pragma unroll
            for (int k = 0; k < PFK; k++)
                if (zsrc_off[k] >= 0) {
                    float4 a = zpn[zsrc_off[k]];
                    float4 c = zpn[zsrc_off[k] + 121];
                    float4* d4 = reinterpret_cast<float4*>(zbn + zdst_off[k]);
                    d4[0] = make_float4(a.x, c.x, a.y, c.y);
                    d4[1] = make_float4(a.z, c.z, a.w, c.w);
                }
            if (xsrc_off >= 0) {
                float4 a = xpn[xsrc_off];
                float4 c = xpn[xsrc_off + 9];
                float4* d4 = reinterpret_cast<float4*>(xbn + xdst_off);
                d4[0] = make_float4(a.x, c.x, a.y, c.y);
                d4[1] = make_float4(a.z, c.z, a.w, c.w);
            }
        }

        // ---- compute from buf[it&1] ----
        {
            const float* zbuf = smem + (it & 1) * BUF_FLOATS;
            const float* xbuf = zbuf + ZBUF_FLOATS;
            const float* zc = zbuf + p * ZPAIR_FLOATS;
            const float* xcp = xbuf + p * XPAIR_FLOATS;
            #pragma unroll
            for (int kk = 0; kk < 3; kk++) {
                const int ky = 3 * h + kk;
                const ull* zrow = reinterpret_cast<const ull*>(
                    zc + (i + ky) * ZROW_PAIRF);
                ull xx[6];
                {
                    const ulonglong2* x2 = reinterpret_cast<const ulonglong2*>(
                        xcp + ky * (KXS * 2));
                    ulonglong2 t0 = x2[0], t1 = x2[1], t2 = x2[2];
                    xx[0] = t0.x; xx[1] = t0.y;
                    xx[2] = t1.x; xx[3] = t1.y;
                    xx[4] = t2.x; xx[5] = t2.y;
                }
                { // half A: positions 0..12
                    ull zp[13];
                    const ulonglong2* z2 = reinterpret_cast<const ulonglong2*>(zrow);
                    #pragma unroll
                    for (int q = 0; q < 6; q++) {
                        ulonglong2 t = z2[q];
                        zp[2*q] = t.x; zp[2*q+1] = t.y;
                    }
                    zp[12] = zrow[12];
                    #pragma unroll
                    for (int kx = 0; kx < KXS; kx++)
                        #pragma unroll
                        for (int j = 0; j <= 12 - kx; j++)
                            fma2(acc[j], zp[j + kx], xx[kx]);
                }
                { // half B: positions 13..21
                    ull zq[9];
                    zq[0] = zrow[13];
                    const ulonglong2* z2 = reinterpret_cast<const ulonglong2*>(zrow + 14);
                    #pragma unroll
                    for (int q = 0; q < 4; q++) {
                        ulonglong2 t = z2[q];
                        zq[1+2*q] = t.x; zq[2+2*q] = t.y;
                    }
                    #pragma unroll
                    for (int kx = 0; kx < KXS; kx++)
                        #pragma unroll
                        for (int j = 13 - kx; j < HO; j++)
                            fma2(acc[j], zq[j + kx - 13], xx[kx]);
                }
            }
        }
        __syncthreads();
    }

    // ---- fold pair lanes, reduce 16 lanes via smem scratch ----
    float* scratch = smem;
    #pragma unroll
    for (int j = 0; j < HO; j++) {
        float lo, hi;
        unpack2(acc[j], lo, hi);
        scratch[lane * OUT_PER_B + i * HO + j] = lo + hi;
    }
    __syncthreads();

    float* ob = out + (size_t)b * OUT_PER_B;
    for (int o = tid; o < OUT_PER_B; o += THREADS) {
        float s = 0.f;
        #pragma unroll
        for (int l = 0; l < LANES; l++)
            s += scratch[l * OUT_PER_B + o];
        ob[o] = s;
    }
}

extern "C" void kernel_launch(void* const* d_in, const int* in_sizes, int n_in,
                              void* d_out, int out_size)
{
    const float* a = (const float*)d_in[0];
    const float* bptr = (const float*)d_in[1];
    const float* x;
    const float* z;
    if (in_sizes[0] == BATCH * CHANNELS * KXS * KXS) { x = a;    z = bptr; }
    else                                             { x = bptr; z = a;   }

    float* out = (float*)d_out;

    cudaFuncSetAttribute(corr_main_kernel,
                         cudaFuncAttributeMaxDynamicSharedMemorySize, SMEM_BYTES);
    corr_main_kernel<<<BATCH, THREADS, SMEM_BYTES>>>(x, z, out);
}

// round 10
// speedup vs baseline: 1.3463x; 1.3463x over previous
#include <cuda_runtime.h>
#include <cstdint>

#define BATCH 512
#define CHANNELS 256
#define KXS 6
#define KZ 22
#define HO 17
#define OUT_PER_B 289
#define N_OUT (BATCH*OUT_PER_B)

#define SPLITS 4
#define CH_PER_SPLIT (CHANNELS/SPLITS)   // 64
#define CH_CHUNK 16                 // 8 pairs per chunk
#define PAIRS_C 8
#define ITERS (CH_PER_SPLIT/CH_CHUNK)    // 4
#define THREADS 272                 // 17 rows x (8 pairs x 2 ky-halves)
#define LANES 16

#define ZPAIR_FLOATS (KZ*KZ*2)      // 968
#define ZROW_PAIRF 44
#define XPAIR_FLOATS (KXS*KXS*2)    // 72
#define ZBUF_FLOATS (PAIRS_C*ZPAIR_FLOATS)   // 7744
#define XBUF_FLOATS (PAIRS_C*XPAIR_FLOATS)   // 576
#define BUF_FLOATS (ZBUF_FLOATS + XBUF_FLOATS)   // 8320
#define SMEM_BYTES (2*BUF_FLOATS*4)              // 66560

#define Z_UNITS (PAIRS_C*121)       // 968
#define X_UNITS (PAIRS_C*9)         // 72
#define PFK 4

// per-chunk slab strides in float4 units
#define ZCHUNK_F4 (CH_CHUNK*KZ*KZ/4)    // 1936
#define XCHUNK_F4 (CH_CHUNK*KXS*KXS/4)  // 144

typedef unsigned long long ull;

__device__ float g_partial[SPLITS * N_OUT];

__device__ __forceinline__ void fma2(ull& d, ull a, ull b) {
    asm("fma.rn.f32x2 %0, %1, %2, %0;" : "+l"(d) : "l"(a), "l"(b));
}
__device__ __forceinline__ void unpack2(ull v, float& lo, float& hi) {
    asm("mov.b64 {%0, %1}, %2;" : "=f"(lo), "=f"(hi) : "l"(v));
}

__global__ __launch_bounds__(THREADS, 2)
void corr_main_kernel(const float* __restrict__ x, const float* __restrict__ z)
{
    extern __shared__ float smem[];   // ping-pong buffers

    const int tid  = threadIdx.x;
    const int i    = tid % HO;        // output row
    const int lane = tid / HO;        // 0..15
    const int p    = lane >> 1;       // pair 0..7
    const int h    = lane & 1;        // ky half
    const int b     = blockIdx.x >> 2;
    const int split = blockIdx.x & 3;
    const int cbase = split * CH_PER_SPLIT;

    // chunk-invariant staging map
    int zsrc_off[PFK], zdst_off[PFK];
    #pragma unroll
    for (int k = 0; k < PFK; k++) {
        int u = tid + k * THREADS;
        if (u < Z_UNITS) {
            int pu = u / 121;
            int w4 = u - pu * 121;
            zsrc_off[k] = 2 * pu * 121 + w4;
            zdst_off[k] = pu * ZPAIR_FLOATS + 8 * w4;
        } else { zsrc_off[k] = -1; zdst_off[k] = 0; }
    }
    int xsrc_off = -1, xdst_off = 0;
    if (tid < X_UNITS) {
        int pu = tid / 9, w4 = tid - pu * 9;
        xsrc_off = 2 * pu * 9 + w4;
        xdst_off = pu * XPAIR_FLOATS + 8 * w4;
    }

    const float4* zg = reinterpret_cast<const float4*>(
        z + ((size_t)b * CHANNELS + cbase) * (KZ * KZ));
    const float4* xg = reinterpret_cast<const float4*>(
        x + ((size_t)b * CHANNELS + cbase) * (KXS * KXS));

    float4 pa[PFK], pc[PFK], xa, xc4;

    // ---- prefetch + store chunk 0 ----
    {
        #pragma unroll
        for (int k = 0; k < PFK; k++)
            if (zsrc_off[k] >= 0) { pa[k] = zg[zsrc_off[k]]; pc[k] = zg[zsrc_off[k] + 121]; }
        if (xsrc_off >= 0) { xa = xg[xsrc_off]; xc4 = xg[xsrc_off + 9]; }

        float* zb0 = smem;
        float* xb0 = smem + ZBUF_FLOATS;
        #pragma unroll
        for (int k = 0; k < PFK; k++)
            if (zsrc_off[k] >= 0) {
                float4* d4 = reinterpret_cast<float4*>(zb0 + zdst_off[k]);
                d4[0] = make_float4(pa[k].x, pc[k].x, pa[k].y, pc[k].y);
                d4[1] = make_float4(pa[k].z, pc[k].z, pa[k].w, pc[k].w);
            }
        if (xsrc_off >= 0) {
            float4* d4 = reinterpret_cast<float4*>(xb0 + xdst_off);
            d4[0] = make_float4(xa.x, xc4.x, xa.y, xc4.y);
            d4[1] = make_float4(xa.z, xc4.z, xa.w, xc4.w);
        }
    }
    __syncthreads();

    ull acc[HO];
    #pragma unroll
    for (int j = 0; j < HO; j++) acc[j] = 0ull;

    #pragma unroll 1
    for (int it = 0; it < ITERS; ++it) {
        // ---- prefetch next chunk into registers (latency hidden by compute) ----
        if (it < ITERS - 1) {
            const float4* zpn = zg + (size_t)(it + 1) * ZCHUNK_F4;
            #pragma unroll
            for (int k = 0; k < PFK; k++)
                if (zsrc_off[k] >= 0) { pa[k] = zpn[zsrc_off[k]]; pc[k] = zpn[zsrc_off[k] + 121]; }
            if (xsrc_off >= 0) {
                const float4* xpn = xg + (size_t)(it + 1) * XCHUNK_F4;
                xa = xpn[xsrc_off]; xc4 = xpn[xsrc_off + 9];
            }
        }

        // ---- compute from buf[it&1] ----
        {
            const float* zbuf = smem + (it & 1) * BUF_FLOATS;
            const float* xbuf = zbuf + ZBUF_FLOATS;
            const float* zc = zbuf + p * ZPAIR_FLOATS;
            const float* xcp = xbuf + p * XPAIR_FLOATS;
            #pragma unroll
            for (int kk = 0; kk < 3; kk++) {
                const int ky = 3 * h + kk;
                const ull* zrow = reinterpret_cast<const ull*>(
                    zc + (i + ky) * ZROW_PAIRF);
                ull xx[6];
                {
                    const ulonglong2* x2 = reinterpret_cast<const ulonglong2*>(
                        xcp + ky * (KXS * 2));
                    ulonglong2 t0 = x2[0], t1 = x2[1], t2 = x2[2];
                    xx[0] = t0.x; xx[1] = t0.y;
                    xx[2] = t1.x; xx[3] = t1.y;
                    xx[4] = t2.x; xx[5] = t2.y;
                }
                { // half A: positions 0..12
                    ull zp[13];
                    const ulonglong2* z2 = reinterpret_cast<const ulonglong2*>(zrow);
                    #pragma unroll
                    for (int q = 0; q < 6; q++) {
                        ulonglong2 t = z2[q];
                        zp[2*q] = t.x; zp[2*q+1] = t.y;
                    }
                    zp[12] = zrow[12];
                    #pragma unroll
                    for (int kx = 0; kx < KXS; kx++)
                        #pragma unroll
                        for (int j = 0; j <= 12 - kx; j++)
                            fma2(acc[j], zp[j + kx], xx[kx]);
                }
                { // half B: positions 13..21
                    ull zq[9];
                    zq[0] = zrow[13];
                    const ulonglong2* z2 = reinterpret_cast<const ulonglong2*>(zrow + 14);
                    #pragma unroll
                    for (int q = 0; q < 4; q++) {
                        ulonglong2 t = z2[q];
                        zq[1+2*q] = t.x; zq[2+2*q] = t.y;
                    }
                    #pragma unroll
                    for (int kx = 0; kx < KXS; kx++)
                        #pragma unroll
                        for (int j = 13 - kx; j < HO; j++)
                            fma2(acc[j], zq[j + kx - 13], xx[kx]);
                }
            }
        }

        // ---- store prefetched chunk into the other buffer ----
        if (it < ITERS - 1) {
            float* zbn = smem + ((it + 1) & 1) * BUF_FLOATS;
            float* xbn = zbn + ZBUF_FLOATS;
            #pragma unroll
            for (int k = 0; k < PFK; k++)
                if (zsrc_off[k] >= 0) {
                    float4* d4 = reinterpret_cast<float4*>(zbn + zdst_off[k]);
                    d4[0] = make_float4(pa[k].x, pc[k].x, pa[k].y, pc[k].y);
                    d4[1] = make_float4(pa[k].z, pc[k].z, pa[k].w, pc[k].w);
                }
            if (xsrc_off >= 0) {
                float4* d4 = reinterpret_cast<float4*>(xbn + xdst_off);
                d4[0] = make_float4(xa.x, xc4.x, xa.y, xc4.y);
                d4[1] = make_float4(xa.z, xc4.z, xa.w, xc4.w);
            }
        }
        __syncthreads();
    }

    // ---- fold pair lanes, reduce 16 lanes via smem scratch ----
    float* scratch = smem;
    #pragma unroll
    for (int j = 0; j < HO; j++) {
        float lo, hi;
        unpack2(acc[j], lo, hi);
        scratch[lane * OUT_PER_B + i * HO + j] = lo + hi;
    }
    __syncthreads();

    for (int o = tid; o < OUT_PER_B; o += THREADS) {
        float s = 0.f;
        #pragma unroll
        for (int l = 0; l < LANES; l++)
            s += scratch[l * OUT_PER_B + o];
        g_partial[((size_t)split * BATCH + b) * OUT_PER_B + o] = s;
    }
}

__global__ void corr_reduce_kernel(float* __restrict__ out)
{
    int idx = blockIdx.x * blockDim.x + threadIdx.x;
    if (idx < N_OUT) {
        out[idx] = g_partial[idx]
                 + g_partial[N_OUT + idx]
                 + g_partial[2 * N_OUT + idx]
                 + g_partial[3 * N_OUT + idx];
    }
}

extern "C" void kernel_launch(void* const* d_in, const int* in_sizes, int n_in,
                              void* d_out, int out_size)
{
    const float* a = (const float*)d_in[0];
    const float* bptr = (const float*)d_in[1];
    const float* x;
    const float* z;
    if (in_sizes[0] == BATCH * CHANNELS * KXS * KXS) { x = a;    z = bptr; }
    else                                             { x = bptr; z = a;   }

    float* out = (float*)d_out;

    cudaFuncSetAttribute(corr_main_kernel,
                         cudaFuncAttributeMaxDynamicSharedMemorySize, SMEM_BYTES);
    corr_main_kernel<<<BATCH * SPLITS, THREADS, SMEM_BYTES>>>(x, z);
    corr_reduce_kernel<<<(N_OUT + 255) / 256, 256>>>(out);
}

// round 11
// speedup vs baseline: 1.4664x; 1.0892x over previous
#include <cuda_runtime.h>
#include <cstdint>

#define BATCH 512
#define CHANNELS 256
#define KXS 6
#define KZ 22
#define HO 17
#define OUT_PER_B 289
#define N_OUT (BATCH*OUT_PER_B)

#define SPLITS 8
#define CH_PER_SPLIT (CHANNELS/SPLITS)   // 32
#define CH_CHUNK 8                  // 4 pairs per chunk
#define PAIRS_C 4
#define ITERS (CH_PER_SPLIT/CH_CHUNK)    // 4
#define THREADS 136                 // 17 rows x (4 pairs x 2 ky-halves)
#define LANES 8

#define ZPAIR_FLOATS (KZ*KZ*2)      // 968
#define ZROW_PAIRF 44
#define XPAIR_FLOATS (KXS*KXS*2)    // 72
#define ZBUF_FLOATS (PAIRS_C*ZPAIR_FLOATS)   // 3872
#define XBUF_FLOATS (PAIRS_C*XPAIR_FLOATS)   // 288
#define BUF_FLOATS (ZBUF_FLOATS + XBUF_FLOATS)   // 4160
#define SMEM_BYTES (2*BUF_FLOATS*4)              // 33280

#define Z_UNITS (PAIRS_C*121)       // 484 float4-pair units per chunk
#define X_UNITS (PAIRS_C*9)         // 36
#define PFK 4                       // 484 = 3*136 + 76

#define ZCHUNK_F4 (CH_CHUNK*KZ*KZ/4)    // 968
#define XCHUNK_F4 (CH_CHUNK*KXS*KXS/4)  // 72

typedef unsigned long long ull;

__device__ float g_partial[SPLITS * N_OUT];

__device__ __forceinline__ void fma2(ull& d, ull a, ull b) {
    asm("fma.rn.f32x2 %0, %1, %2, %0;" : "+l"(d) : "l"(a), "l"(b));
}
__device__ __forceinline__ void unpack2(ull v, float& lo, float& hi) {
    asm("mov.b64 {%0, %1}, %2;" : "=f"(lo), "=f"(hi) : "l"(v));
}

__global__ __launch_bounds__(THREADS, 5)
void corr_main_kernel(const float* __restrict__ x, const float* __restrict__ z)
{
    extern __shared__ float smem[];   // ping-pong buffers

    const int tid  = threadIdx.x;
    const int i    = tid % HO;        // output row
    const int lane = tid / HO;        // 0..7
    const int p    = lane >> 1;       // pair 0..3
    const int h    = lane & 1;        // ky half
    const int b     = blockIdx.x >> 3;
    const int split = blockIdx.x & 7;
    const int cbase = split * CH_PER_SPLIT;

    // chunk-invariant staging map
    int zsrc_off[PFK], zdst_off[PFK];
    #pragma unroll
    for (int k = 0; k < PFK; k++) {
        int u = tid + k * THREADS;
        if (u < Z_UNITS) {
            int pu = u / 121;
            int w4 = u - pu * 121;
            zsrc_off[k] = 2 * pu * 121 + w4;
            zdst_off[k] = pu * ZPAIR_FLOATS + 8 * w4;
        } else { zsrc_off[k] = -1; zdst_off[k] = 0; }
    }
    int xsrc_off = -1, xdst_off = 0;
    if (tid < X_UNITS) {
        int pu = tid / 9, w4 = tid - pu * 9;
        xsrc_off = 2 * pu * 9 + w4;
        xdst_off = pu * XPAIR_FLOATS + 8 * w4;
    }

    const float4* zg = reinterpret_cast<const float4*>(
        z + ((size_t)b * CHANNELS + cbase) * (KZ * KZ));
    const float4* xg = reinterpret_cast<const float4*>(
        x + ((size_t)b * CHANNELS + cbase) * (KXS * KXS));

    // ---- stage chunk 0 into buf0 (inline LDG->interleave->STS) ----
    {
        float* zb0 = smem;
        float* xb0 = smem + ZBUF_FLOATS;
        #pragma unroll
        for (int k = 0; k < PFK; k++)
            if (zsrc_off[k] >= 0) {
                float4 a = zg[zsrc_off[k]];
                float4 c = zg[zsrc_off[k] + 121];
                float4* d4 = reinterpret_cast<float4*>(zb0 + zdst_off[k]);
                d4[0] = make_float4(a.x, c.x, a.y, c.y);
                d4[1] = make_float4(a.z, c.z, a.w, c.w);
            }
        if (xsrc_off >= 0) {
            float4 a = xg[xsrc_off];
            float4 c = xg[xsrc_off + 9];
            float4* d4 = reinterpret_cast<float4*>(xb0 + xdst_off);
            d4[0] = make_float4(a.x, c.x, a.y, c.y);
            d4[1] = make_float4(a.z, c.z, a.w, c.w);
        }
    }
    __syncthreads();

    ull acc[HO];
    #pragma unroll
    for (int j = 0; j < HO; j++) acc[j] = 0ull;

    #pragma unroll 1
    for (int it = 0; it < ITERS; ++it) {
        // ---- stage chunk it+1 into the other buffer (overlap across warps/CTAs) ----
        if (it + 1 < ITERS) {
            const float4* zpn = zg + (size_t)(it + 1) * ZCHUNK_F4;
            const float4* xpn = xg + (size_t)(it + 1) * XCHUNK_F4;
            float* zbn = smem + ((it + 1) & 1) * BUF_FLOATS;
            float* xbn = zbn + ZBUF_FLOATS;
            #pragma unroll
            for (int k = 0; k < PFK; k++)
                if (zsrc_off[k] >= 0) {
                    float4 a = zpn[zsrc_off[k]];
                    float4 c = zpn[zsrc_off[k] + 121];
                    float4* d4 = reinterpret_cast<float4*>(zbn + zdst_off[k]);
                    d4[0] = make_float4(a.x, c.x, a.y, c.y);
                    d4[1] = make_float4(a.z, c.z, a.w, c.w);
                }
            if (xsrc_off >= 0) {
                float4 a = xpn[xsrc_off];
                float4 c = xpn[xsrc_off + 9];
                float4* d4 = reinterpret_cast<float4*>(xbn + xdst_off);
                d4[0] = make_float4(a.x, c.x, a.y, c.y);
                d4[1] = make_float4(a.z, c.z, a.w, c.w);
            }
        }

        // ---- compute from buf[it&1] ----
        {
            const float* zbuf = smem + (it & 1) * BUF_FLOATS;
            const float* xbuf = zbuf + ZBUF_FLOATS;
            const float* zc = zbuf + p * ZPAIR_FLOATS;
            const float* xcp = xbuf + p * XPAIR_FLOATS;
            #pragma unroll
            for (int kk = 0; kk < 3; kk++) {
                const int ky = 3 * h + kk;
                const ull* zrow = reinterpret_cast<const ull*>(
                    zc + (i + ky) * ZROW_PAIRF);
                ull xx[6];
                {
                    const ulonglong2* x2 = reinterpret_cast<const ulonglong2*>(
                        xcp + ky * (KXS * 2));
                    ulonglong2 t0 = x2[0], t1 = x2[1], t2 = x2[2];
                    xx[0] = t0.x; xx[1] = t0.y;
                    xx[2] = t1.x; xx[3] = t1.y;
                    xx[4] = t2.x; xx[5] = t2.y;
                }
                { // half A: positions 0..12
                    ull zp[13];
                    const ulonglong2* z2 = reinterpret_cast<const ulonglong2*>(zrow);
                    #pragma unroll
                    for (int q = 0; q < 6; q++) {
                        ulonglong2 t = z2[q];
                        zp[2*q] = t.x; zp[2*q+1] = t.y;
                    }
                    zp[12] = zrow[12];
                    #pragma unroll
                    for (int kx = 0; kx < KXS; kx++)
                        #pragma unroll
                        for (int j = 0; j <= 12 - kx; j++)
                            fma2(acc[j], zp[j + kx], xx[kx]);
                }
                { // half B: positions 13..21
                    ull zq[9];
                    zq[0] = zrow[13];
                    const ulonglong2* z2 = reinterpret_cast<const ulonglong2*>(zrow + 14);
                    #pragma unroll
                    for (int q = 0; q < 4; q++) {
                        ulonglong2 t = z2[q];
                        zq[1+2*q] = t.x; zq[2+2*q] = t.y;
                    }
                    #pragma unroll
                    for (int kx = 0; kx < KXS; kx++)
                        #pragma unroll
                        for (int j = 13 - kx; j < HO; j++)
                            fma2(acc[j], zq[j + kx - 13], xx[kx]);
                }
            }
        }
        __syncthreads();
    }

    // ---- fold pair lanes, reduce 8 lanes via smem scratch ----
    float* scratch = smem;   // 8*289 = 2312 floats, fits
    #pragma unroll
    for (int j = 0; j < HO; j++) {
        float lo, hi;
        unpack2(acc[j], lo, hi);
        scratch[lane * OUT_PER_B + i * HO + j] = lo + hi;
    }
    __syncthreads();

    for (int o = tid; o < OUT_PER_B; o += THREADS) {
        float s = 0.f;
        #pragma unroll
        for (int l = 0; l < LANES; l++)
            s += scratch[l * OUT_PER_B + o];
        g_partial[((size_t)split * BATCH + b) * OUT_PER_B + o] = s;
    }
}

__global__ void corr_reduce_kernel(float* __restrict__ out)
{
    int idx = blockIdx.x * blockDim.x + threadIdx.x;
    if (idx < N_OUT) {
        float s = 0.f;
        #pragma unroll
        for (int sp = 0; sp < SPLITS; sp++)
            s += g_partial[(size_t)sp * N_OUT + idx];
        out[idx] = s;
    }
}

extern "C" void kernel_launch(void* const* d_in, const int* in_sizes, int n_in,
                              void* d_out, int out_size)
{
    const float* a = (const float*)d_in[0];
    const float* bptr = (const float*)d_in[1];
    const float* x;
    const float* z;
    if (in_sizes[0] == BATCH * CHANNELS * KXS * KXS) { x = a;    z = bptr; }
    else                                             { x = bptr; z = a;   }

    float* out = (float*)d_out;

    cudaFuncSetAttribute(corr_main_kernel,
                         cudaFuncAttributeMaxDynamicSharedMemorySize, SMEM_BYTES);
    corr_main_kernel<<<BATCH * SPLITS, THREADS, SMEM_BYTES>>>(x, z);
    corr_reduce_kernel<<<(N_OUT + 255) / 256, 256>>>(out);
}